// round 2
// baseline (speedup 1.0000x reference)
#include <cuda_runtime.h>

// Problem constants
#define Bc   2
#define Nc   2048
#define Dc   768
#define Hc   12
#define DHc  64
#define Mc   (Bc*Nc)      // 4096
#define S3D  (3*Dc)       // 2304
#define SCALE 0.125f      // 64^-0.5

// Scratch (device globals — no allocation allowed)
__device__ float g_q[Bc*Hc*Nc*DHc];   // [b][h][n][dh]
__device__ float g_k[Bc*Hc*Nc*DHc];
__device__ float g_v[Bc*Hc*Nc*DHc];
__device__ float g_att[Mc*Dc];        // attention output, [b*N+n][h*DH+dh] = row-major [4096][768]

// ---------------------------------------------------------------------------
// QKV GEMM: C[4096,2304] = X[4096,768] @ Wqkv[768,2304] + b, scattered into
// g_q/g_k/g_v with [b][h][n][dh] layout. 64x64 tile, 256 thr, 4x4/thread.
// ---------------------------------------------------------------------------
__global__ __launch_bounds__(256) void qkv_gemm(const float* __restrict__ X,
                                                const float* __restrict__ W,
                                                const float* __restrict__ bias) {
    __shared__ float Xs[32*68];   // transposed: [k][m], pad 68
    __shared__ float Ws[32*68];   // natural:    [k][n], pad 68
    const int tx = threadIdx.x & 15, ty = threadIdx.x >> 4;
    const int m0 = blockIdx.x * 64, n0 = blockIdx.y * 64;
    float acc[4][4] = {};

    for (int k0 = 0; k0 < Dc; k0 += 32) {
        #pragma unroll
        for (int l = 0; l < 8; l++) {
            int idx = threadIdx.x + l*256;
            int mm = idx >> 5, kk = idx & 31;
            Xs[kk*68 + mm] = X[(m0+mm)*Dc + k0 + kk];
        }
        #pragma unroll
        for (int l = 0; l < 8; l++) {
            int idx = threadIdx.x + l*256;
            int kk = idx >> 6, nn = idx & 63;
            Ws[kk*68 + nn] = W[(k0+kk)*S3D + n0 + nn];
        }
        __syncthreads();
        #pragma unroll 8
        for (int kk = 0; kk < 32; kk++) {
            float4 a4 = *(const float4*)&Xs[kk*68 + ty*4];
            float4 b4 = *(const float4*)&Ws[kk*68 + tx*4];
            float a[4] = {a4.x, a4.y, a4.z, a4.w};
            float b[4] = {b4.x, b4.y, b4.z, b4.w};
            #pragma unroll
            for (int i = 0; i < 4; i++)
                #pragma unroll
                for (int j = 0; j < 4; j++)
                    acc[i][j] += a[i]*b[j];
        }
        __syncthreads();
    }

    // Scatter: column g = n0 + tx*4+j; since 64 | n0 and DH=64, the whole
    // block's 64 columns fall in a single (which, head) slice.
    const int which = n0 / Dc;
    const int h = (n0 % Dc) / DHc;
    float* dst = (which == 0) ? g_q : ((which == 1) ? g_k : g_v);
    #pragma unroll
    for (int i = 0; i < 4; i++) {
        int gm = m0 + ty*4 + i;
        int bb = gm >> 11;          // / Nc
        int nn = gm & (Nc-1);
        float* row = dst + ((bb*Hc + h)*Nc + nn)*DHc;
        #pragma unroll
        for (int j = 0; j < 4; j++) {
            int dh = tx*4 + j;
            row[dh] = acc[i][j] + bias[n0 + dh];
        }
    }
}

// ---------------------------------------------------------------------------
// Flash attention: per (b,h) and 64-row Q tile, loop 64-row KV tiles.
// Online softmax kept entirely in registers with 16-lane shfl reductions.
// smem: Qs 16K + KPs 17K (K^T, reused as P) + Vs 8K (half tile) = 41.9 KB.
// ---------------------------------------------------------------------------
__global__ __launch_bounds__(256) void attn64() {
    __shared__ float Qs [64*64];  // natural [m][dh]
    __shared__ float KPs[64*68];  // K^T [dh][n] (pad 68), reused as P [m][n]
    __shared__ float Vs [32*64];  // natural [n][dh], half KV tile

    const int tx = threadIdx.x & 15, ty = threadIdx.x >> 4;
    const int q0 = blockIdx.x * 64;
    const int bh = blockIdx.y;
    const float* Qg = g_q + (size_t)bh * Nc * DHc;
    const float* Kg = g_k + (size_t)bh * Nc * DHc;
    const float* Vg = g_v + (size_t)bh * Nc * DHc;

    #pragma unroll
    for (int l = 0; l < 16; l++) {
        int idx = threadIdx.x + l*256;
        int mm = idx >> 6, dh = idx & 63;
        Qs[mm*64 + dh] = Qg[(q0+mm)*DHc + dh];
    }

    float mi[4], li[4], o[4][4];
    #pragma unroll
    for (int i = 0; i < 4; i++) {
        mi[i] = -1e30f; li[i] = 0.f;
        #pragma unroll
        for (int j = 0; j < 4; j++) o[i][j] = 0.f;
    }

    for (int t = 0; t < Nc/64; t++) {
        const int k0 = t*64;
        // K tile transposed: KPs[dh][n]
        #pragma unroll
        for (int l = 0; l < 16; l++) {
            int idx = threadIdx.x + l*256;
            int mm = idx >> 6, dh = idx & 63;
            KPs[dh*68 + mm] = Kg[(k0+mm)*DHc + dh];
        }
        __syncthreads();

        // S = Q @ K^T  (this thread: rows ty*4+i, cols tx*4+j)
        float s[4][4] = {};
        #pragma unroll 8
        for (int dh = 0; dh < 64; dh++) {
            float4 k4 = *(const float4*)&KPs[dh*68 + tx*4];
            float kv[4] = {k4.x, k4.y, k4.z, k4.w};
            #pragma unroll
            for (int i = 0; i < 4; i++) {
                float qv = Qs[(ty*4+i)*64 + dh];   // broadcast across 16 lanes
                #pragma unroll
                for (int j = 0; j < 4; j++) s[i][j] += qv*kv[j];
            }
        }
        __syncthreads();   // done reading KPs as K

        // Online softmax; row owned by 16 contiguous lanes (xor<=8 stays in group)
        #pragma unroll
        for (int i = 0; i < 4; i++) {
            float rmax = -1e30f;
            #pragma unroll
            for (int j = 0; j < 4; j++) { s[i][j] *= SCALE; rmax = fmaxf(rmax, s[i][j]); }
            for (int off = 8; off > 0; off >>= 1)
                rmax = fmaxf(rmax, __shfl_xor_sync(0xffffffffu, rmax, off));
            float mn  = fmaxf(mi[i], rmax);
            float fac = __expf(mi[i] - mn);
            float rs  = 0.f;
            #pragma unroll
            for (int j = 0; j < 4; j++) { s[i][j] = __expf(s[i][j] - mn); rs += s[i][j]; }
            for (int off = 8; off > 0; off >>= 1)
                rs += __shfl_xor_sync(0xffffffffu, rs, off);
            li[i] = li[i]*fac + rs;
            #pragma unroll
            for (int j = 0; j < 4; j++) o[i][j] *= fac;
            mi[i] = mn;
        }

        // Write P into the (dead) K buffer: P[m][n]
        #pragma unroll
        for (int i = 0; i < 4; i++)
            *(float4*)&KPs[(ty*4+i)*68 + tx*4] =
                make_float4(s[i][0], s[i][1], s[i][2], s[i][3]);

        // O += P @ V, V streamed in two 32-row halves (keeps smem < 48K)
        #pragma unroll
        for (int half = 0; half < 2; half++) {
            #pragma unroll
            for (int l = 0; l < 8; l++) {
                int idx = threadIdx.x + l*256;
                int mm = idx >> 6, dh = idx & 63;
                Vs[mm*64 + dh] = Vg[(k0 + half*32 + mm)*DHc + dh];
            }
            __syncthreads();   // V visible; also makes P visible on half 0
            #pragma unroll 8
            for (int nn = 0; nn < 32; nn++) {
                float4 v4 = *(const float4*)&Vs[nn*64 + tx*4];
                float vv[4] = {v4.x, v4.y, v4.z, v4.w};
                #pragma unroll
                for (int i = 0; i < 4; i++) {
                    float p = KPs[(ty*4+i)*68 + half*32 + nn];  // broadcast
                    #pragma unroll
                    for (int j = 0; j < 4; j++) o[i][j] += p*vv[j];
                }
            }
            __syncthreads();   // reads done before Vs/KPs are overwritten
        }
    }

    // Epilogue: attn output laid out directly as [b][n][h*DH+dh]
    const int b = bh / Hc, h = bh % Hc;
    #pragma unroll
    for (int i = 0; i < 4; i++) {
        float inv = 1.f / li[i];
        int nn = q0 + ty*4 + i;
        float* row = g_att + ((size_t)(b*Nc + nn))*Dc + h*DHc;
        #pragma unroll
        for (int j = 0; j < 4; j++)
            row[tx*4 + j] = o[i][j] * inv;
    }
}

// ---------------------------------------------------------------------------
// Output projection: out[4096,768] = g_att[4096,768] @ Wproj[768,768] + b
// ---------------------------------------------------------------------------
__global__ __launch_bounds__(256) void proj_gemm(const float* __restrict__ W,
                                                 const float* __restrict__ bias,
                                                 float* __restrict__ out) {
    __shared__ float As[32*68];
    __shared__ float Ws[32*68];
    const int tx = threadIdx.x & 15, ty = threadIdx.x >> 4;
    const int m0 = blockIdx.x * 64, n0 = blockIdx.y * 64;
    float acc[4][4] = {};

    for (int k0 = 0; k0 < Dc; k0 += 32) {
        #pragma unroll
        for (int l = 0; l < 8; l++) {
            int idx = threadIdx.x + l*256;
            int mm = idx >> 5, kk = idx & 31;
            As[kk*68 + mm] = g_att[(size_t)(m0+mm)*Dc + k0 + kk];
        }
        #pragma unroll
        for (int l = 0; l < 8; l++) {
            int idx = threadIdx.x + l*256;
            int kk = idx >> 6, nn = idx & 63;
            Ws[kk*68 + nn] = W[(k0+kk)*Dc + n0 + nn];
        }
        __syncthreads();
        #pragma unroll 8
        for (int kk = 0; kk < 32; kk++) {
            float4 a4 = *(const float4*)&As[kk*68 + ty*4];
            float4 b4 = *(const float4*)&Ws[kk*68 + tx*4];
            float a[4] = {a4.x, a4.y, a4.z, a4.w};
            float b[4] = {b4.x, b4.y, b4.z, b4.w};
            #pragma unroll
            for (int i = 0; i < 4; i++)
                #pragma unroll
                for (int j = 0; j < 4; j++)
                    acc[i][j] += a[i]*b[j];
        }
        __syncthreads();
    }

    #pragma unroll
    for (int i = 0; i < 4; i++) {
        int gm = m0 + ty*4 + i;
        #pragma unroll
        for (int j = 0; j < 4; j++) {
            int gn = n0 + tx*4 + j;
            out[(size_t)gm*Dc + gn] = acc[i][j] + bias[gn];
        }
    }
}

// ---------------------------------------------------------------------------
extern "C" void kernel_launch(void* const* d_in, const int* in_sizes, int n_in,
                              void* d_out, int out_size) {
    const float* x      = (const float*)d_in[0];
    const float* w_qkv  = (const float*)d_in[1];
    const float* b_qkv  = (const float*)d_in[2];
    const float* w_proj = (const float*)d_in[3];
    const float* b_proj = (const float*)d_in[4];
    float* out = (float*)d_out;

    qkv_gemm<<<dim3(Mc/64, S3D/64), 256>>>(x, w_qkv, b_qkv);
    attn64  <<<dim3(Nc/64, Bc*Hc),  256>>>();
    proj_gemm<<<dim3(Mc/64, Dc/64), 256>>>(w_proj, b_proj, out);
}

// round 4
// speedup vs baseline: 3.0957x; 3.0957x over previous
#include <cuda_runtime.h>

#define NSEQ  2048
#define DMODEL 768
#define NH    12
#define DH    64
#define BATCH 2
#define MROWS 4096          // BATCH*NSEQ
#define S3DIM 2304          // 3*DMODEL
#define SCALE 0.125f        // DH^-0.5

// Scratch (tf32 bit patterns stored as unsigned)
__device__ unsigned g_q[BATCH*NH*NSEQ*DH];
__device__ unsigned g_k[BATCH*NH*NSEQ*DH];
__device__ unsigned g_v[BATCH*NH*NSEQ*DH];
__device__ unsigned g_att[MROWS*DMODEL];

__device__ __forceinline__ unsigned f2t(float f){
    unsigned u; asm("cvt.rna.tf32.f32 %0, %1;" : "=r"(u) : "f"(f)); return u;
}
__device__ __forceinline__ void mma_tf32(float c[4], const unsigned a[4], const unsigned b[2]){
    asm volatile("mma.sync.aligned.m16n8k8.row.col.f32.tf32.tf32.f32 "
        "{%0,%1,%2,%3}, {%4,%5,%6,%7}, {%8,%9}, {%0,%1,%2,%3};"
        : "+f"(c[0]), "+f"(c[1]), "+f"(c[2]), "+f"(c[3])
        : "r"(a[0]), "r"(a[1]), "r"(a[2]), "r"(a[3]), "r"(b[0]), "r"(b[1]));
}

// ---------------------------------------------------------------------------
// QKV GEMM: [4096,768] @ [768,2304] -> scatter tf32 into g_q/g_k/g_v [b][h][n][dh]
// CTA 128x128, 8 warps (4m x 2n), warp tile 32x64, k-chunk 32.
// ---------------------------------------------------------------------------
__global__ __launch_bounds__(256) void qkv_mma(const float* __restrict__ X,
                                               const float* __restrict__ W,
                                               const float* __restrict__ bias){
    __shared__ unsigned As[128*36];
    __shared__ unsigned Bs[32*132];
    const int tid = threadIdx.x, lane = tid & 31, warp = tid >> 5;
    const int wm = (warp >> 1) * 32, wn = (warp & 1) * 64;
    const int m0 = blockIdx.x * 128, n0 = blockIdx.y * 128;
    float c[2][8][4] = {};

    for (int k0 = 0; k0 < DMODEL; k0 += 32){
        #pragma unroll
        for (int l = 0; l < 4; l++){
            int idx = tid + l*256;
            int mm = idx >> 3, c4 = (idx & 7)*4;
            float4 v = *(const float4*)&X[(size_t)(m0+mm)*DMODEL + k0 + c4];
            unsigned* d = &As[mm*36 + c4];
            d[0]=f2t(v.x); d[1]=f2t(v.y); d[2]=f2t(v.z); d[3]=f2t(v.w);
        }
        #pragma unroll
        for (int l = 0; l < 4; l++){
            int idx = tid + l*256;
            int kk = idx >> 5, c4 = (idx & 31)*4;
            float4 v = *(const float4*)&W[(size_t)(k0+kk)*S3DIM + n0 + c4];
            unsigned* d = &Bs[kk*132 + c4];
            d[0]=f2t(v.x); d[1]=f2t(v.y); d[2]=f2t(v.z); d[3]=f2t(v.w);
        }
        __syncthreads();
        #pragma unroll
        for (int ks = 0; ks < 32; ks += 8){
            unsigned a[2][4];
            #pragma unroll
            for (int i = 0; i < 2; i++){
                int r = wm + i*16 + (lane>>2);
                a[i][0] = As[r*36     + ks + (lane&3)];
                a[i][1] = As[(r+8)*36 + ks + (lane&3)];
                a[i][2] = As[r*36     + ks + (lane&3) + 4];
                a[i][3] = As[(r+8)*36 + ks + (lane&3) + 4];
            }
            #pragma unroll
            for (int j = 0; j < 8; j++){
                unsigned b[2];
                b[0] = Bs[(ks + (lane&3))*132     + wn + j*8 + (lane>>2)];
                b[1] = Bs[(ks + (lane&3) + 4)*132 + wn + j*8 + (lane>>2)];
                mma_tf32(c[0][j], a[0], b);
                mma_tf32(c[1][j], a[1], b);
            }
        }
        __syncthreads();
    }
    // epilogue: scatter into g_q/g_k/g_v, q pre-scaled by SCALE (exact pow2)
    #pragma unroll
    for (int j = 0; j < 8; j++){
        int n_abs = n0 + wn + j*8;
        int which = n_abs / DMODEL;
        int rem = n_abs - which*DMODEL;
        int h = rem >> 6;
        int dh0 = (rem & 63) + 2*(lane&3);
        unsigned* dst = (which==0) ? g_q : (which==1 ? g_k : g_v);
        float sc = (which==0) ? SCALE : 1.0f;
        float b0 = bias[n_abs + 2*(lane&3)], b1 = bias[n_abs + 2*(lane&3) + 1];
        #pragma unroll
        for (int i = 0; i < 2; i++){
            int gm = m0 + wm + i*16 + (lane>>2);
            #pragma unroll
            for (int half = 0; half < 2; half++){
                int r = gm + half*8;
                int bb = r >> 11, nn = r & (NSEQ-1);
                unsigned* row = dst + ((size_t)((bb*NH + h)*NSEQ + nn))*DH + dh0;
                row[0] = f2t((c[i][j][half*2+0] + b0) * sc);
                row[1] = f2t((c[i][j][half*2+1] + b1) * sc);
            }
        }
    }
}

// ---------------------------------------------------------------------------
// Flash attention, tensor-core. CTA: one (b,h), 128 Q rows. 8 warps, each owns
// 16 S/O rows. KV tiles of 64. Online softmax in registers (quad shfl).
// Dynamic smem: Qs[128][68] Ks[64][68] Vs[64][68] Ps[128][68] = 104448 B.
// ---------------------------------------------------------------------------
__global__ __launch_bounds__(256) void attn_mma(){
    extern __shared__ unsigned sm[];
    unsigned* Qs = sm;               // [128][68]
    unsigned* Ks = Qs + 128*68;      // [64][68]
    unsigned* Vs = Ks + 64*68;       // [64][68]
    unsigned* Ps = Vs + 64*68;       // [128][68]
    const int tid = threadIdx.x, lane = tid & 31, warp = tid >> 5;
    const int q0 = blockIdx.x * 128;
    const int bh = blockIdx.y;
    const unsigned* Qg = g_q + (size_t)bh*NSEQ*DH;
    const unsigned* Kg = g_k + (size_t)bh*NSEQ*DH;
    const unsigned* Vg = g_v + (size_t)bh*NSEQ*DH;

    #pragma unroll
    for (int l = 0; l < 8; l++){
        int idx = tid + l*256;
        int mm = idx >> 4, c4 = (idx & 15)*4;
        uint4 v = *(const uint4*)&Qg[(size_t)(q0+mm)*DH + c4];
        unsigned* d = &Qs[mm*68 + c4];
        d[0]=v.x; d[1]=v.y; d[2]=v.z; d[3]=v.w;
    }

    float o[8][4] = {};
    float mi0 = -1e30f, mi1 = -1e30f, li0 = 0.f, li1 = 0.f;
    const int r0 = warp*16 + (lane>>2);

    for (int t = 0; t < NSEQ/64; t++){
        __syncthreads();   // prior PV reads of Vs done (covers initial Qs too)
        #pragma unroll
        for (int l = 0; l < 4; l++){
            int idx = tid + l*256;
            int nn = idx >> 4, c4 = (idx & 15)*4;
            uint4 kv = *(const uint4*)&Kg[(size_t)(t*64+nn)*DH + c4];
            unsigned* d = &Ks[nn*68 + c4];
            d[0]=kv.x; d[1]=kv.y; d[2]=kv.z; d[3]=kv.w;
            uint4 vv = *(const uint4*)&Vg[(size_t)(t*64+nn)*DH + c4];
            unsigned* e = &Vs[nn*68 + c4];
            e[0]=vv.x; e[1]=vv.y; e[2]=vv.z; e[3]=vv.w;
        }
        __syncthreads();

        // S = Q @ K^T  (Q pre-scaled)
        float s[8][4] = {};
        #pragma unroll
        for (int d8 = 0; d8 < 64; d8 += 8){
            unsigned a[4];
            a[0] = Qs[r0*68     + d8 + (lane&3)];
            a[1] = Qs[(r0+8)*68 + d8 + (lane&3)];
            a[2] = Qs[r0*68     + d8 + (lane&3) + 4];
            a[3] = Qs[(r0+8)*68 + d8 + (lane&3) + 4];
            #pragma unroll
            for (int j = 0; j < 8; j++){
                unsigned b[2];
                b[0] = Ks[(j*8 + (lane>>2))*68 + d8 + (lane&3)];
                b[1] = Ks[(j*8 + (lane>>2))*68 + d8 + (lane&3) + 4];
                mma_tf32(s[j], a, b);
            }
        }

        // online softmax: rows r0 (c0,c1) and r0+8 (c2,c3)
        float rm0 = -1e30f, rm1 = -1e30f;
        #pragma unroll
        for (int j = 0; j < 8; j++){
            rm0 = fmaxf(rm0, fmaxf(s[j][0], s[j][1]));
            rm1 = fmaxf(rm1, fmaxf(s[j][2], s[j][3]));
        }
        rm0 = fmaxf(rm0, __shfl_xor_sync(0xffffffffu, rm0, 1));
        rm0 = fmaxf(rm0, __shfl_xor_sync(0xffffffffu, rm0, 2));
        rm1 = fmaxf(rm1, __shfl_xor_sync(0xffffffffu, rm1, 1));
        rm1 = fmaxf(rm1, __shfl_xor_sync(0xffffffffu, rm1, 2));
        float mn0 = fmaxf(mi0, rm0), mn1 = fmaxf(mi1, rm1);
        float f0 = __expf(mi0 - mn0), f1 = __expf(mi1 - mn1);
        float sum0 = 0.f, sum1 = 0.f;
        #pragma unroll
        for (int j = 0; j < 8; j++){
            s[j][0] = __expf(s[j][0]-mn0); s[j][1] = __expf(s[j][1]-mn0);
            s[j][2] = __expf(s[j][2]-mn1); s[j][3] = __expf(s[j][3]-mn1);
            sum0 += s[j][0]+s[j][1];       sum1 += s[j][2]+s[j][3];
            o[j][0]*=f0; o[j][1]*=f0; o[j][2]*=f1; o[j][3]*=f1;
        }
        sum0 += __shfl_xor_sync(0xffffffffu, sum0, 1);
        sum0 += __shfl_xor_sync(0xffffffffu, sum0, 2);
        sum1 += __shfl_xor_sync(0xffffffffu, sum1, 1);
        sum1 += __shfl_xor_sync(0xffffffffu, sum1, 2);
        li0 = li0*f0 + sum0; li1 = li1*f1 + sum1;
        mi0 = mn0; mi1 = mn1;

        // write P (own 16 rows only -> warp-local)
        #pragma unroll
        for (int j = 0; j < 8; j++){
            int cc = j*8 + 2*(lane&3);
            Ps[r0*68 + cc]       = f2t(s[j][0]);
            Ps[r0*68 + cc + 1]   = f2t(s[j][1]);
            Ps[(r0+8)*68 + cc]   = f2t(s[j][2]);
            Ps[(r0+8)*68 + cc+1] = f2t(s[j][3]);
        }
        __syncwarp();

        // O += P @ V
        #pragma unroll
        for (int kn = 0; kn < 64; kn += 8){
            unsigned a[4];
            a[0] = Ps[r0*68     + kn + (lane&3)];
            a[1] = Ps[(r0+8)*68 + kn + (lane&3)];
            a[2] = Ps[r0*68     + kn + (lane&3) + 4];
            a[3] = Ps[(r0+8)*68 + kn + (lane&3) + 4];
            #pragma unroll
            for (int j = 0; j < 8; j++){
                unsigned b[2];
                b[0] = Vs[(kn + (lane&3))*68     + j*8 + (lane>>2)];
                b[1] = Vs[(kn + (lane&3) + 4)*68 + j*8 + (lane>>2)];
                mma_tf32(o[j], a, b);
            }
        }
    }

    // epilogue -> g_att[b*N+n][h*64+dh] as tf32 bits
    const int b = bh / NH, h = bh % NH;
    float inv0 = 1.f/li0, inv1 = 1.f/li1;
    #pragma unroll
    for (int j = 0; j < 8; j++){
        int dh = j*8 + 2*(lane&3);
        int row0 = q0 + r0, row1 = row0 + 8;
        unsigned* p0 = g_att + ((size_t)(b*NSEQ + row0))*DMODEL + h*DH + dh;
        unsigned* p1 = g_att + ((size_t)(b*NSEQ + row1))*DMODEL + h*DH + dh;
        p0[0] = f2t(o[j][0]*inv0); p0[1] = f2t(o[j][1]*inv0);
        p1[0] = f2t(o[j][2]*inv1); p1[1] = f2t(o[j][3]*inv1);
    }
}

// ---------------------------------------------------------------------------
// Output projection: out[4096,768] = g_att @ Wproj + b   (same scheme as qkv)
// ---------------------------------------------------------------------------
__global__ __launch_bounds__(256) void proj_mma(const float* __restrict__ W,
                                                const float* __restrict__ bias,
                                                float* __restrict__ out){
    __shared__ unsigned As[128*36];
    __shared__ unsigned Bs[32*132];
    const int tid = threadIdx.x, lane = tid & 31, warp = tid >> 5;
    const int wm = (warp >> 1) * 32, wn = (warp & 1) * 64;
    const int m0 = blockIdx.x * 128, n0 = blockIdx.y * 128;
    float c[2][8][4] = {};

    for (int k0 = 0; k0 < DMODEL; k0 += 32){
        #pragma unroll
        for (int l = 0; l < 4; l++){
            int idx = tid + l*256;
            int mm = idx >> 3, c4 = (idx & 7)*4;
            uint4 v = *(const uint4*)&g_att[(size_t)(m0+mm)*DMODEL + k0 + c4];
            unsigned* d = &As[mm*36 + c4];
            d[0]=v.x; d[1]=v.y; d[2]=v.z; d[3]=v.w;
        }
        #pragma unroll
        for (int l = 0; l < 4; l++){
            int idx = tid + l*256;
            int kk = idx >> 5, c4 = (idx & 31)*4;
            float4 v = *(const float4*)&W[(size_t)(k0+kk)*DMODEL + n0 + c4];
            unsigned* d = &Bs[kk*132 + c4];
            d[0]=f2t(v.x); d[1]=f2t(v.y); d[2]=f2t(v.z); d[3]=f2t(v.w);
        }
        __syncthreads();
        #pragma unroll
        for (int ks = 0; ks < 32; ks += 8){
            unsigned a[2][4];
            #pragma unroll
            for (int i = 0; i < 2; i++){
                int r = wm + i*16 + (lane>>2);
                a[i][0] = As[r*36     + ks + (lane&3)];
                a[i][1] = As[(r+8)*36 + ks + (lane&3)];
                a[i][2] = As[r*36     + ks + (lane&3) + 4];
                a[i][3] = As[(r+8)*36 + ks + (lane&3) + 4];
            }
            #pragma unroll
            for (int j = 0; j < 8; j++){
                unsigned b[2];
                b[0] = Bs[(ks + (lane&3))*132     + wn + j*8 + (lane>>2)];
                b[1] = Bs[(ks + (lane&3) + 4)*132 + wn + j*8 + (lane>>2)];
                mma_tf32(c[0][j], a[0], b);
                mma_tf32(c[1][j], a[1], b);
            }
        }
        __syncthreads();
    }
    #pragma unroll
    for (int j = 0; j < 8; j++){
        int gn = n0 + wn + j*8 + 2*(lane&3);
        float b0 = bias[gn], b1 = bias[gn+1];
        #pragma unroll
        for (int i = 0; i < 2; i++){
            int gm = m0 + wm + i*16 + (lane>>2);
            #pragma unroll
            for (int half = 0; half < 2; half++){
                float* p = &out[(size_t)(gm + half*8)*DMODEL + gn];
                p[0] = c[i][j][half*2+0] + b0;
                p[1] = c[i][j][half*2+1] + b1;
            }
        }
    }
}

// ---------------------------------------------------------------------------
extern "C" void kernel_launch(void* const* d_in, const int* in_sizes, int n_in,
                              void* d_out, int out_size) {
    const float* x      = (const float*)d_in[0];
    const float* w_qkv  = (const float*)d_in[1];
    const float* b_qkv  = (const float*)d_in[2];
    const float* w_proj = (const float*)d_in[3];
    const float* b_proj = (const float*)d_in[4];
    float* out = (float*)d_out;

    const int attn_smem = (128*68 + 64*68 + 64*68 + 128*68) * 4;  // 104448
    cudaFuncSetAttribute(attn_mma, cudaFuncAttributeMaxDynamicSharedMemorySize, attn_smem);

    qkv_mma <<<dim3(32, 18), 256>>>(x, w_qkv, b_qkv);
    attn_mma<<<dim3(16, 24), 256, attn_smem>>>();
    proj_mma<<<dim3(32, 6),  256>>>(w_proj, b_proj, out);
}